// round 13
// baseline (speedup 1.0000x reference)
#include <cuda_runtime.h>
#include <stdint.h>

// MeanAggregator: out[b, :] = mean over {neighbours[b,0..9], nodes[b]} of features[idx, :]
// B = 100000, K = 10, N = 1000000, D = 128 (fp32). Indices int32 (JAX x64 disabled).
//
// HALF D-split (2 passes x 256 B per row): 256B-contiguous misses -> ~80% DRAM util.
// L2 repeat capture measured AT the residency bound (68% vs 69% theoretical) — policy
// and traffic levers exhausted. This round finishes the occupancy curve: gathers in
// 4+4+3 batches (peak 16 live v-regs) + launch_bounds(256,8) -> 32 regs, 8 CTAs/SM.
//
// Warp = 2 rows: 2 subgroups of 16 lanes; lane = one float4 of the 16-float4 half-row.
// Output via st.global.wt (L2 write-bypass), indices streaming (__ldcs).

#define B_NODES   100000
#define K_NEIGH   10
#define D_DIM     128
#define D_VEC     (D_DIM / 4)    // 32 float4 per row
#define H_VEC     16             // 16 float4 per half

__device__ __forceinline__ void stg_wt(float4* p, float4 v) {
    asm volatile("st.global.wt.v4.f32 [%0], {%1, %2, %3, %4};"
                 :: "l"(p), "f"(v.x), "f"(v.y), "f"(v.z), "f"(v.w)
                 : "memory");
}

__global__ __launch_bounds__(256, 8)
void mean_agg_kernel(const int*    __restrict__ nodes,
                     const int*    __restrict__ neighbours,
                     const float4* __restrict__ features,
                     float4*       __restrict__ out)
{
    const int warp = (blockIdx.x * blockDim.x + threadIdx.x) >> 5;  // 0..49999
    const int lane = threadIdx.x & 31;
    const int sub  = lane >> 4;        // subgroup 0..1 -> row offset
    const int sl   = lane & 15;        // float4 slot within half-row
    const int q    = blockIdx.y;       // feature-dim half (slowest-varying)

    const int row = warp * 2 + sub;
    if (row >= B_NODES) return;

    const float4* fq = features + q * H_VEC + sl;

    float4 acc = make_float4(0.f, 0.f, 0.f, 0.f);

    // Batch A: neighbours 0..3
    {
        int   i0 = __ldcs(&neighbours[row * K_NEIGH + 0]);
        int   i1 = __ldcs(&neighbours[row * K_NEIGH + 1]);
        int   i2 = __ldcs(&neighbours[row * K_NEIGH + 2]);
        int   i3 = __ldcs(&neighbours[row * K_NEIGH + 3]);
        float4 v0 = __ldg(fq + (long long)i0 * D_VEC);
        float4 v1 = __ldg(fq + (long long)i1 * D_VEC);
        float4 v2 = __ldg(fq + (long long)i2 * D_VEC);
        float4 v3 = __ldg(fq + (long long)i3 * D_VEC);
        acc.x += v0.x + v1.x + v2.x + v3.x;
        acc.y += v0.y + v1.y + v2.y + v3.y;
        acc.z += v0.z + v1.z + v2.z + v3.z;
        acc.w += v0.w + v1.w + v2.w + v3.w;
    }

    // Batch B: neighbours 4..7
    {
        int   i0 = __ldcs(&neighbours[row * K_NEIGH + 4]);
        int   i1 = __ldcs(&neighbours[row * K_NEIGH + 5]);
        int   i2 = __ldcs(&neighbours[row * K_NEIGH + 6]);
        int   i3 = __ldcs(&neighbours[row * K_NEIGH + 7]);
        float4 v0 = __ldg(fq + (long long)i0 * D_VEC);
        float4 v1 = __ldg(fq + (long long)i1 * D_VEC);
        float4 v2 = __ldg(fq + (long long)i2 * D_VEC);
        float4 v3 = __ldg(fq + (long long)i3 * D_VEC);
        acc.x += v0.x + v1.x + v2.x + v3.x;
        acc.y += v0.y + v1.y + v2.y + v3.y;
        acc.z += v0.z + v1.z + v2.z + v3.z;
        acc.w += v0.w + v1.w + v2.w + v3.w;
    }

    // Batch C: neighbours 8..9 + self node
    {
        int   i0 = __ldcs(&neighbours[row * K_NEIGH + 8]);
        int   i1 = __ldcs(&neighbours[row * K_NEIGH + 9]);
        int   i2 = __ldcs(&nodes[row]);
        float4 v0 = __ldg(fq + (long long)i0 * D_VEC);
        float4 v1 = __ldg(fq + (long long)i1 * D_VEC);
        float4 v2 = __ldg(fq + (long long)i2 * D_VEC);
        acc.x += v0.x + v1.x + v2.x;
        acc.y += v0.y + v1.y + v2.y;
        acc.z += v0.z + v1.z + v2.z;
        acc.w += v0.w + v1.w + v2.w;
    }

    const float s = 1.0f / (float)(K_NEIGH + 1);
    acc.x *= s; acc.y *= s; acc.z *= s; acc.w *= s;

    stg_wt(&out[(long long)row * D_VEC + q * H_VEC + sl], acc);
}

extern "C" void kernel_launch(void* const* d_in, const int* in_sizes, int n_in,
                              void* d_out, int out_size)
{
    const int*    nodes      = (const int*)d_in[0];
    const int*    neighbours = (const int*)d_in[1];
    const float4* features   = (const float4*)d_in[2];
    float4*       out        = (float4*)d_out;

    const int threads = 256;
    const int warps_needed = (B_NODES + 1) / 2;                       // 50000
    dim3 grid((warps_needed * 32 + threads - 1) / threads, 2);        // 6250 x 2
    mean_agg_kernel<<<grid, threads>>>(nodes, neighbours, features, out);
}